// round 1
// baseline (speedup 1.0000x reference)
#include <cuda_runtime.h>
#include <cuda_bf16.h>
#include <mma.h>
#include <math.h>

using namespace nvcuda;

#define T_TOK 2048
#define H_DIM 2048
#define I_DIM 4096
#define NEXP  8

// ---------------- device scratch (no allocations allowed) ----------------
__device__ __align__(16) float d_xs [T_TOK * H_DIM];        // 16 MB: score-scaled gathered input (grouped by expert)
__device__ __align__(16) float d_gu [T_TOK * 2 * I_DIM];    // 64 MB: routed gate_up output (grouped rows)
__device__ __align__(16) float d_act[T_TOK * I_DIM];        // 32 MB: routed swiglu activation (grouped rows)
__device__ __align__(16) float d_g  [T_TOK * I_DIM];        // 32 MB: shared gate (then reused as shared act)
__device__ __align__(16) float d_u  [T_TOK * I_DIM];        // 32 MB: shared up
__device__ float d_score[T_TOK];
__device__ int   d_eid[T_TOK];
__device__ int   d_order[T_TOK];
__device__ int   d_cnt[NEXP];
__device__ int   d_off[NEXP + 1];
__device__ int   d_cnt2[NEXP];

// ---------------- small kernels ----------------
__global__ void init_kernel() {
    if (threadIdx.x < NEXP) { d_cnt[threadIdx.x] = 0; d_cnt2[threadIdx.x] = 0; }
}

__global__ void router_kernel(const float* __restrict__ x, const float* __restrict__ rw) {
    int t = blockIdx.x;
    const float* xr = x + (size_t)t * H_DIM;
    float acc[NEXP];
#pragma unroll
    for (int e = 0; e < NEXP; e++) acc[e] = 0.f;
    for (int h = threadIdx.x; h < H_DIM; h += blockDim.x) {
        float xv = xr[h];
#pragma unroll
        for (int e = 0; e < NEXP; e++) acc[e] = fmaf(xv, rw[e * H_DIM + h], acc[e]);
    }
    __shared__ float red[8][NEXP];
    int lane = threadIdx.x & 31, w = threadIdx.x >> 5;
#pragma unroll
    for (int e = 0; e < NEXP; e++) {
        float v = acc[e];
#pragma unroll
        for (int o = 16; o > 0; o >>= 1) v += __shfl_down_sync(0xffffffffu, v, o);
        if (lane == 0) red[w][e] = v;
    }
    __syncthreads();
    if (threadIdx.x == 0) {
        float best = -1e30f; int bi = 0;
#pragma unroll
        for (int e = 0; e < NEXP; e++) {
            float v = 0.f;
#pragma unroll
            for (int w2 = 0; w2 < 8; w2++) v += red[w2][e];
            if (v > best) { best = v; bi = e; }
        }
        d_eid[t] = bi;
        d_score[t] = 1.f / (1.f + expf(-best));
        atomicAdd(&d_cnt[bi], 1);
    }
}

__global__ void offsets_kernel() {
    if (threadIdx.x == 0) {
        int s = 0;
        for (int e = 0; e < NEXP; e++) { d_off[e] = s; s += d_cnt[e]; }
        d_off[NEXP] = s;
    }
}

__global__ void gather_kernel(const float* __restrict__ x) {
    int t = blockIdx.x;
    __shared__ int spos; __shared__ float ss;
    if (threadIdx.x == 0) {
        int e = d_eid[t];
        int p = atomicAdd(&d_cnt2[e], 1) + d_off[e];
        d_order[p] = t; spos = p; ss = d_score[t];
    }
    __syncthreads();
    int p = spos; float s = ss;
    const float4* src = (const float4*)(x + (size_t)t * H_DIM);
    float4* dst = (float4*)(d_xs + (size_t)p * H_DIM);
    for (int i = threadIdx.x; i < H_DIM / 4; i += blockDim.x) {
        float4 v = src[i];
        v.x *= s; v.y *= s; v.z *= s; v.w *= s;
        dst[i] = v;
    }
}

__device__ __forceinline__ float silu_f(float g) { return g / (1.f + expf(-g)); }

__global__ void swiglu_routed_kernel() {
    int idx = blockIdx.x * blockDim.x + threadIdx.x;
    const int total4 = T_TOK * I_DIM / 4;
    if (idx >= total4) return;
    int row = idx / (I_DIM / 4);
    int c4  = idx % (I_DIM / 4);
    const float4* gp = (const float4*)(d_gu + (size_t)row * 2 * I_DIM);
    float4 g = gp[c4];
    float4 u = gp[c4 + I_DIM / 4];
    float4 r;
    r.x = u.x * silu_f(g.x);
    r.y = u.y * silu_f(g.y);
    r.z = u.z * silu_f(g.z);
    r.w = u.w * silu_f(g.w);
    ((float4*)d_act)[idx] = r;
}

__global__ void swiglu_shared_kernel() {
    int idx = blockIdx.x * blockDim.x + threadIdx.x;
    const int total4 = T_TOK * I_DIM / 4;
    if (idx >= total4) return;
    float4 g = ((const float4*)d_g)[idx];
    float4 u = ((const float4*)d_u)[idx];
    float4 r;
    r.x = u.x * silu_f(g.x);
    r.y = u.y * silu_f(g.y);
    r.z = u.z * silu_f(g.z);
    r.w = u.w * silu_f(g.w);
    ((float4*)d_g)[idx] = r;
}

// ---------------- generic tf32 wmma GEMM ----------------
// C[M,N] (+)= A[M,K] * B[K,N], all row-major fp32 in gmem, tf32 tensor compute.
// expert_mode: blockIdx.x = e*16 + mblk; rows for expert e are d_cnt[e] starting
// at grouped row d_off[e]; B += e*bStride. remap: C row = d_order[off+local].
#define BM 128
#define BN 128
#define BK 32
#define AS_LD 36
#define BS_LD 132

__global__ __launch_bounds__(256, 2)
void gemm_tf32(const float* __restrict__ A, int lda,
               const float* __restrict__ B, int ldb, long long bStride,
               float* __restrict__ C, int ldc,
               int M, int N, int K,
               int expert_mode, int remap, int accumulate)
{
    __shared__ float As[BM][AS_LD];
    __shared__ float Bs[BK][BS_LD];
    __shared__ float stage[8][16 * 20];

    int mblk = blockIdx.x;
    const int* rowmap = nullptr;
    int row_base = 0;
    int Mloc = M;
    if (expert_mode) {
        const int mbPerE = (T_TOK + BM - 1) / BM;  // 16
        int e = blockIdx.x / mbPerE;
        mblk = blockIdx.x % mbPerE;
        Mloc = d_cnt[e];
        if (mblk * BM >= Mloc) return;
        A += (size_t)d_off[e] * lda;
        B += (size_t)e * bStride;
        if (remap) rowmap = d_order + d_off[e];
        else       row_base = d_off[e];
    }
    const int row0 = mblk * BM;
    const int n0 = blockIdx.y * BN;
    const int tid = threadIdx.x;
    const int warp = tid >> 5;
    const int wm = warp & 3;   // 4 warps along M (32 rows each)
    const int wn = warp >> 2;  // 2 warps along N (64 cols each)

    wmma::fragment<wmma::accumulator, 16, 16, 8, float> c[2][4];
#pragma unroll
    for (int mi = 0; mi < 2; mi++)
#pragma unroll
        for (int ni = 0; ni < 4; ni++)
            wmma::fill_fragment(c[mi][ni], 0.f);

    for (int k0 = 0; k0 < K; k0 += BK) {
        // load A tile [BM x BK]
#pragma unroll
        for (int i = 0; i < 4; i++) {
            int r  = (tid >> 3) + i * 32;
            int c4 = (tid & 7) * 4;
            float4 v = make_float4(0.f, 0.f, 0.f, 0.f);
            if (row0 + r < Mloc)
                v = *(const float4*)(A + (size_t)(row0 + r) * lda + k0 + c4);
            *(float4*)(&As[r][c4]) = v;
        }
        // load B tile [BK x BN]
#pragma unroll
        for (int i = 0; i < 4; i++) {
            int r  = (tid >> 5) + i * 8;
            int c4 = (tid & 31) * 4;
            float4 v = *(const float4*)(B + (size_t)(k0 + r) * ldb + n0 + c4);
            *(float4*)(&Bs[r][c4]) = v;
        }
        __syncthreads();
#pragma unroll
        for (int kk = 0; kk < BK / 8; kk++) {
            wmma::fragment<wmma::matrix_a, 16, 16, 8, wmma::precision::tf32, wmma::row_major> a[2];
            wmma::fragment<wmma::matrix_b, 16, 16, 8, wmma::precision::tf32, wmma::row_major> b[4];
#pragma unroll
            for (int mi = 0; mi < 2; mi++) {
                wmma::load_matrix_sync(a[mi], &As[wm * 32 + mi * 16][kk * 8], AS_LD);
#pragma unroll
                for (int el = 0; el < a[mi].num_elements; el++)
                    a[mi].x[el] = wmma::__float_to_tf32(a[mi].x[el]);
            }
#pragma unroll
            for (int ni = 0; ni < 4; ni++) {
                wmma::load_matrix_sync(b[ni], &Bs[kk * 8][wn * 64 + ni * 16], BS_LD);
#pragma unroll
                for (int el = 0; el < b[ni].num_elements; el++)
                    b[ni].x[el] = wmma::__float_to_tf32(b[ni].x[el]);
            }
#pragma unroll
            for (int mi = 0; mi < 2; mi++)
#pragma unroll
                for (int ni = 0; ni < 4; ni++)
                    wmma::mma_sync(c[mi][ni], a[mi], b[ni], c[mi][ni]);
        }
        __syncthreads();
    }

    // epilogue: stage per-warp in smem, then (optionally remapped / accumulated) global write
    const int lane = tid & 31;
#pragma unroll
    for (int mi = 0; mi < 2; mi++) {
#pragma unroll
        for (int ni = 0; ni < 4; ni++) {
            wmma::store_matrix_sync(&stage[warp][0], c[mi][ni], 20, wmma::mem_row_major);
            __syncwarp();
#pragma unroll
            for (int j = 0; j < 8; j++) {
                int idx = lane * 8 + j;        // 0..255
                int r = idx >> 4, cc = idx & 15;
                int gloc = row0 + wm * 32 + mi * 16 + r;
                if (gloc < Mloc) {
                    int grow = rowmap ? rowmap[gloc] : (row_base + gloc);
                    int gcol = n0 + wn * 64 + ni * 16 + cc;
                    float v = stage[warp][r * 20 + cc];
                    float* p = C + (size_t)grow * ldc + gcol;
                    if (accumulate) *p += v; else *p = v;
                }
            }
            __syncwarp();
        }
    }
}

// ---------------- launch ----------------
extern "C" void kernel_launch(void* const* d_in, const int* in_sizes, int n_in,
                              void* d_out, int out_size)
{
    const float* x   = (const float*)d_in[0];   // [T, H]
    const float* rw  = (const float*)d_in[1];   // [E, H]
    const float* gup = (const float*)d_in[2];   // [E, H, 2I]
    const float* dwn = (const float*)d_in[3];   // [E, I, H]
    const float* sg  = (const float*)d_in[4];   // [H, I]
    const float* su  = (const float*)d_in[5];   // [H, I]
    const float* sd  = (const float*)d_in[6];   // [I, H]
    float* out = (float*)d_out;                  // [T, H]

    void *p_xs, *p_gu, *p_act, *p_g, *p_u;
    cudaGetSymbolAddress(&p_xs,  d_xs);
    cudaGetSymbolAddress(&p_gu,  d_gu);
    cudaGetSymbolAddress(&p_act, d_act);
    cudaGetSymbolAddress(&p_g,   d_g);
    cudaGetSymbolAddress(&p_u,   d_u);

    // 1) routing
    init_kernel<<<1, 32>>>();
    router_kernel<<<T_TOK, 256>>>(x, rw);
    offsets_kernel<<<1, 1>>>();
    gather_kernel<<<T_TOK, 256>>>(x);

    const int sw_blocks = (T_TOK * I_DIM / 4 + 255) / 256;

    // 2) shared expert: gate, up, swiglu, down(out =)
    gemm_tf32<<<dim3(T_TOK / BM, I_DIM / BN), 256>>>(
        x, H_DIM, sg, I_DIM, 0, (float*)p_g, I_DIM, T_TOK, I_DIM, H_DIM, 0, 0, 0);
    gemm_tf32<<<dim3(T_TOK / BM, I_DIM / BN), 256>>>(
        x, H_DIM, su, I_DIM, 0, (float*)p_u, I_DIM, T_TOK, I_DIM, H_DIM, 0, 0, 0);
    swiglu_shared_kernel<<<sw_blocks, 256>>>();
    gemm_tf32<<<dim3(T_TOK / BM, H_DIM / BN), 256>>>(
        (const float*)p_g, I_DIM, sd, H_DIM, 0, out, H_DIM, T_TOK, H_DIM, I_DIM, 0, 0, 0);

    // 3) routed experts (grouped rows): gate_up, swiglu, down(out +=, scattered)
    gemm_tf32<<<dim3(NEXP * (T_TOK / BM), 2 * I_DIM / BN), 256>>>(
        (const float*)p_xs, H_DIM, gup, 2 * I_DIM, (long long)H_DIM * 2 * I_DIM,
        (float*)p_gu, 2 * I_DIM, T_TOK, 2 * I_DIM, H_DIM, 1, 0, 0);
    swiglu_routed_kernel<<<sw_blocks, 256>>>();
    gemm_tf32<<<dim3(NEXP * (T_TOK / BM), H_DIM / BN), 256>>>(
        (const float*)p_act, I_DIM, dwn, H_DIM, (long long)I_DIM * H_DIM,
        out, H_DIM, T_TOK, H_DIM, I_DIM, 1, 1, 1);
}